// round 3
// baseline (speedup 1.0000x reference)
#include <cuda_runtime.h>
#include <math.h>
#include <stdint.h>

// Problem constants
#define T_TOK 16384
#define DIM   1024
#define DFF   4096
#define NE    8
#define CAP   3277          // ceil(16384 * 1.6 / 8)
#define NOISE_STD 0.02f

// ---------------- device scratch (no allocations allowed) ----------------
__device__ int   g_top1[T_TOK];
__device__ int   g_top2[T_TOK];
__device__ int   g_win [T_TOK];          // max accepted expert per token, -1 = none
__device__ int   g_idx [NE][CAP];        // per-expert ordered token list
__device__ int   g_cnt [NE];             // min(matched, CAP)
__device__ float g_H   [(size_t)NE * CAP * DFF];   // gelu(x@w1+b1), ~430 MB

// =====================================================================
// Router: logits = x @ rw^T + rb + noise*0.02 ; top-2 (ties -> lower idx)
// One warp per token, 8 warps per block.
// =====================================================================
__global__ void router_kernel(const float* __restrict__ x,
                              const float* __restrict__ rw,
                              const float* __restrict__ rb,
                              const float* __restrict__ noise)
{
    __shared__ float s_rw[NE * DIM];
    for (int i = threadIdx.x; i < NE * DIM; i += blockDim.x) s_rw[i] = rw[i];
    __syncthreads();

    int warp = threadIdx.x >> 5;
    int lane = threadIdx.x & 31;
    int t = blockIdx.x * 8 + warp;
    if (t >= T_TOK) return;

    float acc[NE];
#pragma unroll
    for (int e = 0; e < NE; e++) acc[e] = 0.f;

    const float* xr = x + (size_t)t * DIM;
#pragma unroll 4
    for (int i = lane; i < DIM; i += 32) {
        float xv = xr[i];
#pragma unroll
        for (int e = 0; e < NE; e++) acc[e] += xv * s_rw[e * DIM + i];
    }
#pragma unroll
    for (int e = 0; e < NE; e++) {
#pragma unroll
        for (int off = 16; off > 0; off >>= 1)
            acc[e] += __shfl_xor_sync(0xFFFFFFFFu, acc[e], off);
    }

    if (lane == 0) {
        float lg[NE];
#pragma unroll
        for (int e = 0; e < NE; e++)
            lg[e] = acc[e] + rb[e] + noise[t * NE + e] * NOISE_STD;

        // argmax, first-index-wins on ties (matches jax top_k ordering)
        int b1i = 0; float b1v = lg[0];
#pragma unroll
        for (int e = 1; e < NE; e++) if (lg[e] > b1v) { b1v = lg[e]; b1i = e; }
        int b2i = -1; float b2v = -3.4e38f;
#pragma unroll
        for (int e = 0; e < NE; e++)
            if (e != b1i && lg[e] > b2v) { b2v = lg[e]; b2i = e; }

        g_top1[t] = b1i;
        g_top2[t] = b2i;
        g_win[t]  = -1;
    }
}

// =====================================================================
// Assignment: for each expert, ordered compaction of matching tokens,
// keep first CAP (token order). Record winner = max accepted expert.
// One block (1024 threads) per expert, 16 sequential chunks of 1024.
// =====================================================================
__global__ void assign_kernel()
{
    int e    = blockIdx.x;
    int tid  = threadIdx.x;
    int lane = tid & 31;
    int w    = tid >> 5;

    __shared__ int s_wsum[32];
    __shared__ int s_total;

    int base = 0;
    for (int chunk = 0; chunk < T_TOK / 1024; chunk++) {
        int t = chunk * 1024 + tid;
        int flag = (g_top1[t] == e) || (g_top2[t] == e);

        unsigned bal = __ballot_sync(0xFFFFFFFFu, flag);
        int wpre = __popc(bal & ((1u << lane) - 1u));
        if (lane == 0) s_wsum[w] = __popc(bal);
        __syncthreads();

        if (w == 0) {
            int v = s_wsum[lane];
            int inc = v;
#pragma unroll
            for (int off = 1; off < 32; off <<= 1) {
                int o = __shfl_up_sync(0xFFFFFFFFu, inc, off);
                if (lane >= off) inc += o;
            }
            s_wsum[lane] = inc - v;          // exclusive prefix
            if (lane == 31) s_total = inc;
        }
        __syncthreads();

        if (flag) {
            int pos = base + s_wsum[w] + wpre;
            if (pos < CAP) {
                g_idx[e][pos] = t;
                atomicMax(&g_win[t], e);     // later experts overwrite earlier
            }
        }
        base += s_total;
        __syncthreads();
    }
    if (tid == 0) g_cnt[e] = base < CAP ? base : CAP;
}

// =====================================================================
// SGEMM tiles: 128x128x8, 256 threads, 8x8 microtile, float4 everywhere.
// =====================================================================
#define BM 128
#define BN 128
#define BK 8

// GEMM1: H[s,f] = gelu( x[idx[e][s]] @ w1[e] + b1[e] )   (M=cnt,N=4096,K=1024)
__global__ __launch_bounds__(256) void gemm1_kernel(
    const float* __restrict__ x,
    const float* __restrict__ w1,
    const float* __restrict__ b1)
{
    int e   = blockIdx.z;
    int cnt = g_cnt[e];
    int m0  = blockIdx.y * BM;
    if (m0 >= cnt) return;
    int n0  = blockIdx.x * BN;

    __shared__ __align__(16) float As[BK][BM + 4];
    __shared__ __align__(16) float Bs[BK][BN + 4];

    int tid = threadIdx.x;
    int tx  = tid & 15;       // n
    int ty  = tid >> 4;       // m

    // A loader: 1 float4 per thread
    int ar = tid >> 1;                 // 0..127
    int ak = (tid & 1) * 4;            // 0 or 4
    int arow = m0 + ar;
    const float* Aptr = nullptr;
    if (arow < cnt) {
        int tok = g_idx[e][arow];
        Aptr = x + (size_t)tok * DIM + ak;
    }
    // B loader: 1 float4 per thread
    int bk = tid >> 5;                 // 0..7
    int bn = (tid & 31) * 4;           // 0..124
    const float* Bptr = w1 + (size_t)e * DIM * DFF + (size_t)bk * DFF + n0 + bn;

    float acc[8][8];
#pragma unroll
    for (int i = 0; i < 8; i++)
#pragma unroll
        for (int j = 0; j < 8; j++) acc[i][j] = 0.f;

    for (int kt = 0; kt < DIM; kt += BK) {
        float4 av = Aptr ? *(const float4*)(Aptr + kt) : make_float4(0.f,0.f,0.f,0.f);
        float4 bv = *(const float4*)(Bptr + (size_t)kt * DFF);
        As[ak+0][ar] = av.x; As[ak+1][ar] = av.y;
        As[ak+2][ar] = av.z; As[ak+3][ar] = av.w;
        *(float4*)&Bs[bk][bn] = bv;
        __syncthreads();

#pragma unroll
        for (int k = 0; k < BK; k++) {
            float4 a0 = *(const float4*)&As[k][ty * 8];
            float4 a1 = *(const float4*)&As[k][ty * 8 + 4];
            float4 b0 = *(const float4*)&Bs[k][tx * 8];
            float4 b1v= *(const float4*)&Bs[k][tx * 8 + 4];
            float a[8] = {a0.x,a0.y,a0.z,a0.w,a1.x,a1.y,a1.z,a1.w};
            float b[8] = {b0.x,b0.y,b0.z,b0.w,b1v.x,b1v.y,b1v.z,b1v.w};
#pragma unroll
            for (int i = 0; i < 8; i++)
#pragma unroll
                for (int j = 0; j < 8; j++) acc[i][j] += a[i] * b[j];
        }
        __syncthreads();
    }

    // epilogue: + b1, exact gelu, store to g_H
#pragma unroll
    for (int i = 0; i < 8; i++) {
        int s = m0 + ty * 8 + i;
        if (s >= cnt) continue;
        float* hrow = g_H + ((size_t)e * CAP + s) * DFF + n0 + tx * 8;
        float o[8];
#pragma unroll
        for (int j = 0; j < 8; j++) {
            float v = acc[i][j] + b1[e * DFF + n0 + tx * 8 + j];
            o[j] = 0.5f * v * (1.0f + erff(v * 0.70710678118654752f));
        }
        *(float4*)&hrow[0] = make_float4(o[0], o[1], o[2], o[3]);
        *(float4*)&hrow[4] = make_float4(o[4], o[5], o[6], o[7]);
    }
}

// GEMM2: eo[s,d] = H[s] @ w2[e] + b2[e]; write out[t] only if winner(t)==e.
// (M=cnt, N=1024, K=4096)
__global__ __launch_bounds__(256) void gemm2_kernel(
    const float* __restrict__ w2,
    const float* __restrict__ b2,
    float* __restrict__ out)
{
    int e   = blockIdx.z;
    int cnt = g_cnt[e];
    int m0  = blockIdx.y * BM;
    if (m0 >= cnt) return;
    int n0  = blockIdx.x * BN;

    __shared__ __align__(16) float As[BK][BM + 4];
    __shared__ __align__(16) float Bs[BK][BN + 4];

    int tid = threadIdx.x;
    int tx  = tid & 15;
    int ty  = tid >> 4;

    int ar = tid >> 1;
    int ak = (tid & 1) * 4;
    int arow = m0 + ar;
    const float* Aptr = nullptr;
    if (arow < cnt)
        Aptr = g_H + ((size_t)e * CAP + arow) * DFF + ak;

    int bk = tid >> 5;
    int bn = (tid & 31) * 4;
    const float* Bptr = w2 + (size_t)e * DFF * DIM + (size_t)bk * DIM + n0 + bn;

    float acc[8][8];
#pragma unroll
    for (int i = 0; i < 8; i++)
#pragma unroll
        for (int j = 0; j < 8; j++) acc[i][j] = 0.f;

    for (int kt = 0; kt < DFF; kt += BK) {
        float4 av = Aptr ? *(const float4*)(Aptr + kt) : make_float4(0.f,0.f,0.f,0.f);
        float4 bv = *(const float4*)(Bptr + (size_t)kt * DIM);
        As[ak+0][ar] = av.x; As[ak+1][ar] = av.y;
        As[ak+2][ar] = av.z; As[ak+3][ar] = av.w;
        *(float4*)&Bs[bk][bn] = bv;
        __syncthreads();

#pragma unroll
        for (int k = 0; k < BK; k++) {
            float4 a0 = *(const float4*)&As[k][ty * 8];
            float4 a1 = *(const float4*)&As[k][ty * 8 + 4];
            float4 b0 = *(const float4*)&Bs[k][tx * 8];
            float4 b1v= *(const float4*)&Bs[k][tx * 8 + 4];
            float a[8] = {a0.x,a0.y,a0.z,a0.w,a1.x,a1.y,a1.z,a1.w};
            float b[8] = {b0.x,b0.y,b0.z,b0.w,b1v.x,b1v.y,b1v.z,b1v.w};
#pragma unroll
            for (int i = 0; i < 8; i++)
#pragma unroll
                for (int j = 0; j < 8; j++) acc[i][j] += a[i] * b[j];
        }
        __syncthreads();
    }

#pragma unroll
    for (int i = 0; i < 8; i++) {
        int s = m0 + ty * 8 + i;
        if (s >= cnt) continue;
        int t = g_idx[e][s];
        if (g_win[t] != e) continue;     // exactly one winner writes each token
        float* orow = out + (size_t)t * DIM + n0 + tx * 8;
        float o[8];
#pragma unroll
        for (int j = 0; j < 8; j++)
            o[j] = acc[i][j] + b2[e * DIM + n0 + tx * 8 + j];
        *(float4*)&orow[0] = make_float4(o[0], o[1], o[2], o[3]);
        *(float4*)&orow[4] = make_float4(o[4], o[5], o[6], o[7]);
    }
}

// =====================================================================
// Launch (graph-capturable: kernels + async memset only, default stream)
// =====================================================================
extern "C" void kernel_launch(void* const* d_in, const int* in_sizes, int n_in,
                              void* d_out, int out_size)
{
    const float* x     = (const float*)d_in[0];
    const float* noise = (const float*)d_in[1];
    const float* rw    = (const float*)d_in[2];
    const float* rb    = (const float*)d_in[3];
    const float* w1    = (const float*)d_in[4];
    const float* b1    = (const float*)d_in[5];
    const float* w2    = (const float*)d_in[6];
    const float* b2    = (const float*)d_in[7];
    float* out = (float*)d_out;

    // dropped tokens must be zero; d_out is poisoned before timing
    cudaMemsetAsync(d_out, 0, (size_t)out_size * sizeof(float), 0);

    router_kernel<<<T_TOK / 8, 256>>>(x, rw, rb, noise);
    assign_kernel<<<NE, 1024>>>();

    dim3 g1(DFF / BN, (CAP + BM - 1) / BM, NE);   // 32 x 26 x 8
    gemm1_kernel<<<g1, 256>>>(x, w1, b1);

    dim3 g2(DIM / BN, (CAP + BM - 1) / BM, NE);   // 8 x 26 x 8
    gemm2_kernel<<<g2, 256>>>(w2, b2, out);
}

// round 11
// speedup vs baseline: 3.9665x; 3.9665x over previous
#include <cuda_runtime.h>
#include <math.h>
#include <stdint.h>

// Problem constants
#define T_TOK 16384
#define DIM   1024
#define DFF   4096
#define NE    8
#define CAP   3277          // ceil(16384 * 1.6 / 8)
#define NOISE_STD 0.02f

// ---------------- device scratch (no allocations allowed) ----------------
__device__ int   g_top1[T_TOK];
__device__ int   g_top2[T_TOK];
__device__ int   g_win [T_TOK];          // max accepted expert per token, -1 = none
__device__ int   g_idx [NE][CAP];        // per-expert ordered token list
__device__ int   g_cnt [NE];             // min(matched, CAP)
__device__ float g_H [(size_t)NE * CAP * DFF];    // gelu(x@w1+b1), tf32-rounded
__device__ float g_X [(size_t)T_TOK * DIM];       // tf32-rounded x
__device__ float g_W1[(size_t)NE * DIM * DFF];    // tf32-rounded w1
__device__ float g_W2[(size_t)NE * DFF * DIM];    // tf32-rounded w2

// =====================================================================
// PTX helpers (sm_80-level only: works on compute_103 base target)
// =====================================================================
__device__ __forceinline__ uint32_t smem_u32(const void* p) {
    uint32_t a;
    asm("{ .reg .u64 t; cvta.to.shared.u64 t, %1; cvt.u32.u64 %0, t; }"
        : "=r"(a) : "l"(p));
    return a;
}
__device__ __forceinline__ uint32_t f2tf(float f) {   // fp32 -> tf32 (round-nearest)
    uint32_t r; asm("cvt.rna.tf32.f32 %0, %1;" : "=r"(r) : "f"(f)); return r;
}
__device__ __forceinline__ void cpa16(uint32_t sdst, const void* gsrc) {
    asm volatile("cp.async.cg.shared.global [%0], [%1], 16;"
                 :: "r"(sdst), "l"(gsrc));
}
#define CP_COMMIT() asm volatile("cp.async.commit_group;" ::: "memory")
#define CP_WAIT1()  asm volatile("cp.async.wait_group 1;" ::: "memory")

// D[16x8] += A[16x8] * B[8x8], tf32 inputs (b32 regs), fp32 accum
__device__ __forceinline__ void mma8(float* d, const uint32_t* a, const uint32_t* b) {
    asm volatile(
        "mma.sync.aligned.m16n8k8.row.col.f32.tf32.tf32.f32 "
        "{%0,%1,%2,%3},{%4,%5,%6,%7},{%8,%9},{%0,%1,%2,%3};"
        : "+f"(d[0]), "+f"(d[1]), "+f"(d[2]), "+f"(d[3])
        : "r"(a[0]), "r"(a[1]), "r"(a[2]), "r"(a[3]), "r"(b[0]), "r"(b[1]));
}

// =====================================================================
// Elementwise fp32 -> tf32 rounding (pre-pass for x, w1, w2)
// =====================================================================
__global__ void cvt_tf32_kernel(const float4* __restrict__ src,
                                float4* __restrict__ dst, int n4)
{
    int i = blockIdx.x * blockDim.x + threadIdx.x;
    int stride = gridDim.x * blockDim.x;
    for (; i < n4; i += stride) {
        float4 v = src[i];
        dst[i] = make_float4(__uint_as_float(f2tf(v.x)),
                             __uint_as_float(f2tf(v.y)),
                             __uint_as_float(f2tf(v.z)),
                             __uint_as_float(f2tf(v.w)));
    }
}

// =====================================================================
// Router: logits = x @ rw^T + rb + noise*0.02 ; top-2 (ties -> lower idx)
// =====================================================================
__global__ void router_kernel(const float* __restrict__ x,
                              const float* __restrict__ rw,
                              const float* __restrict__ rb,
                              const float* __restrict__ noise)
{
    __shared__ float s_rw[NE * DIM];
    for (int i = threadIdx.x; i < NE * DIM; i += blockDim.x) s_rw[i] = rw[i];
    __syncthreads();

    int warp = threadIdx.x >> 5;
    int lane = threadIdx.x & 31;
    int t = blockIdx.x * 8 + warp;
    if (t >= T_TOK) return;

    float acc[NE];
#pragma unroll
    for (int e = 0; e < NE; e++) acc[e] = 0.f;

    const float* xr = x + (size_t)t * DIM;
#pragma unroll 4
    for (int i = lane; i < DIM; i += 32) {
        float xv = xr[i];
#pragma unroll
        for (int e = 0; e < NE; e++) acc[e] += xv * s_rw[e * DIM + i];
    }
#pragma unroll
    for (int e = 0; e < NE; e++) {
#pragma unroll
        for (int off = 16; off > 0; off >>= 1)
            acc[e] += __shfl_xor_sync(0xFFFFFFFFu, acc[e], off);
    }

    if (lane == 0) {
        float lg[NE];
#pragma unroll
        for (int e = 0; e < NE; e++)
            lg[e] = acc[e] + rb[e] + noise[t * NE + e] * NOISE_STD;

        int b1i = 0; float b1v = lg[0];
#pragma unroll
        for (int e = 1; e < NE; e++) if (lg[e] > b1v) { b1v = lg[e]; b1i = e; }
        int b2i = -1; float b2v = -3.4e38f;
#pragma unroll
        for (int e = 0; e < NE; e++)
            if (e != b1i && lg[e] > b2v) { b2v = lg[e]; b2i = e; }

        g_top1[t] = b1i;
        g_top2[t] = b2i;
        g_win[t]  = -1;
    }
}

// =====================================================================
// Assignment: per-expert ordered compaction, first CAP kept, winner = max e
// =====================================================================
__global__ void assign_kernel()
{
    int e    = blockIdx.x;
    int tid  = threadIdx.x;
    int lane = tid & 31;
    int w    = tid >> 5;

    __shared__ int s_wsum[32];
    __shared__ int s_total;

    int base = 0;
    for (int chunk = 0; chunk < T_TOK / 1024; chunk++) {
        int t = chunk * 1024 + tid;
        int flag = (g_top1[t] == e) || (g_top2[t] == e);

        unsigned bal = __ballot_sync(0xFFFFFFFFu, flag);
        int wpre = __popc(bal & ((1u << lane) - 1u));
        if (lane == 0) s_wsum[w] = __popc(bal);
        __syncthreads();

        if (w == 0) {
            int v = s_wsum[lane];
            int inc = v;
#pragma unroll
            for (int off = 1; off < 32; off <<= 1) {
                int o = __shfl_up_sync(0xFFFFFFFFu, inc, off);
                if (lane >= off) inc += o;
            }
            s_wsum[lane] = inc - v;
            if (lane == 31) s_total = inc;
        }
        __syncthreads();

        if (flag) {
            int pos = base + s_wsum[w] + wpre;
            if (pos < CAP) {
                g_idx[e][pos] = t;
                atomicMax(&g_win[t], e);
            }
        }
        base += s_total;
        __syncthreads();
    }
    if (tid == 0) g_cnt[e] = base < CAP ? base : CAP;
}

// =====================================================================
// tf32 mma.sync GEMM: CTA tile 128x128x32, 4 warps (2x2), warp tile 64x64.
// cp.async double-buffered. A rows gathered (G1: tokens, G2: H rows).
//   G1: H = tf32round( gelu( gather(gX) @ gW1 + b1 ) )   K=1024, N=4096
//   G2: out[winner rows] = H @ gW2 + b2                  K=4096, N=1024
//
// k-permutation: mma physical k-slot p <- logical k = 2*(p%4) + (p>>2),
// applied identically to A and B fragments (dot product invariant).
// =====================================================================
#define BM 128
#define BN 128
#define BK 32
#define NTHR 128
#define A_STAGE 16384                 // BM rows x 128B (XOR-swizzled 16B chunks)
#define B_ROWB  528                   // (BN + 4 pad) * 4B
#define B_STAGE (BK * B_ROWB)         // 16896
#define STAGE_B (A_STAGE + B_STAGE)   // 33280
#define GEMM_DSM (2 * STAGE_B)        // 66560

template<int KTOT, int NTOT, bool IS_G1>
__global__ __launch_bounds__(NTHR, 2) void moe_gemm(
    const float* __restrict__ W,       // tf32-rounded weights [E][KTOT][NTOT]
    const float* __restrict__ bias,    // [E][NTOT] (fp32)
    float* __restrict__ Oout)          // out (G2) / unused (G1)
{
    const int e   = blockIdx.z;
    const int cnt = g_cnt[e];
    const int m0  = blockIdx.y * BM;
    if (m0 >= cnt) return;
    const int n0  = blockIdx.x * BN;

    extern __shared__ char dsm[];
    const uint32_t sbase = smem_u32(dsm);

    __shared__ int s_tok[BM];

    const int tid = threadIdx.x;
    {
        int m = m0 + tid; if (m >= cnt) m = cnt - 1;
        s_tok[tid] = g_idx[e][m];
    }
    __syncthreads();

    // ---- cp.async A: chunk col = tid&7 (16B), rows (tid>>3) + 16*i ----
    const int a_c  = tid & 7;
    const int a_r0 = tid >> 3;
    const uint32_t a_swz = ((uint32_t)(a_c ^ (a_r0 & 7)) << 4);
    const char* a_src[8];
    const uint32_t a_dst0 = sbase + a_r0 * 128 + a_swz;
#pragma unroll
    for (int i = 0; i < 8; i++) {
        int r = a_r0 + 16 * i;
        const float* rowp;
        if (IS_G1) {
            rowp = g_X + (size_t)s_tok[r] * KTOT;
        } else {
            int m = m0 + r; if (m >= cnt) m = cnt - 1;
            rowp = g_H + ((size_t)e * CAP + m) * KTOT;
        }
        a_src[i] = (const char*)rowp + a_c * 16;
    }
    // ---- cp.async B: col chunk tid&31 (16B), k rows (tid>>5) + 4*i ----
    const int b_j  = tid & 31;
    const int b_k0 = tid >> 5;
    const char* b_src0 = (const char*)(W + ((size_t)e * KTOT + b_k0) * NTOT
                                       + n0 + b_j * 4);
    const uint32_t b_dst0 = sbase + A_STAGE + b_k0 * B_ROWB + b_j * 16;

    // ---- fragment indexing ----
    const int lane = tid & 31;
    const int wid  = tid >> 5;
    const int g    = lane >> 2;       // group 0..7
    const int tg   = lane & 3;        // thread-in-group 0..3
    const int warp_m = (wid >> 1) * 64;
    const int warp_n = (wid & 1) * 64;

    float d[4][8][4];
#pragma unroll
    for (int mt = 0; mt < 4; mt++)
#pragma unroll
        for (int nt = 0; nt < 8; nt++)
#pragma unroll
            for (int q = 0; q < 4; q++) d[mt][nt][q] = 0.f;

    const int S = KTOT / BK;

    // prologue: stage 0
    {
        const size_t bks = (size_t)4 * NTOT * 4;
#pragma unroll
        for (int i = 0; i < 8; i++) cpa16(a_dst0 + i * 2048u, a_src[i]);
#pragma unroll
        for (int i = 0; i < 8; i++) cpa16(b_dst0 + i * 4u * B_ROWB, b_src0 + i * bks);
    }
    CP_COMMIT();

    for (int s = 0; s < S; s++) {
        if (s + 1 < S) {
            const uint32_t soff = (uint32_t)((s + 1) & 1) * STAGE_B;
            const size_t akoff = (size_t)(s + 1) * (BK * 4);
            const size_t bkoff = (size_t)(s + 1) * ((size_t)BK * NTOT * 4);
            const size_t bks   = (size_t)4 * NTOT * 4;
#pragma unroll
            for (int i = 0; i < 8; i++)
                cpa16(a_dst0 + soff + i * 2048u, a_src[i] + akoff);
#pragma unroll
            for (int i = 0; i < 8; i++)
                cpa16(b_dst0 + soff + i * 4u * B_ROWB, b_src0 + bkoff + i * bks);
        }
        CP_COMMIT();
        CP_WAIT1();
        __syncthreads();

        const uint32_t sA = sbase + (uint32_t)(s & 1) * STAGE_B;
        const uint32_t sB = sA + A_STAGE;

#pragma unroll
        for (int ks = 0; ks < 4; ks++) {
            uint32_t a[4][4];
#pragma unroll
            for (int mt = 0; mt < 4; mt++) {
                uint32_t rb_ = sA + (uint32_t)(warp_m + mt * 16 + g) * 128u
                             + ((uint32_t)((2 * ks + (tg >> 1)) ^ g) << 4)
                             + (uint32_t)(tg & 1) * 8u;
                asm("ld.shared.v2.b32 {%0,%1},[%2];"
                    : "=r"(a[mt][0]), "=r"(a[mt][2]) : "r"(rb_));
                asm("ld.shared.v2.b32 {%0,%1},[%2];"
                    : "=r"(a[mt][1]), "=r"(a[mt][3]) : "r"(rb_ + 8u * 128u));
            }
            uint32_t b[8][2];
#pragma unroll
            for (int nt = 0; nt < 8; nt++) {
                uint32_t cb = sB + (uint32_t)(8 * ks + 2 * tg) * B_ROWB
                            + (uint32_t)(warp_n + nt * 8 + g) * 4u;
                asm("ld.shared.b32 %0,[%1];" : "=r"(b[nt][0]) : "r"(cb));
                asm("ld.shared.b32 %0,[%1];" : "=r"(b[nt][1]) : "r"(cb + B_ROWB));
            }
#pragma unroll
            for (int mt = 0; mt < 4; mt++)
#pragma unroll
                for (int nt = 0; nt < 8; nt++)
                    mma8(d[mt][nt], a[mt], b[nt]);
        }
        __syncthreads();
    }

    // ---- epilogue ----
    const float* bv = bias + (size_t)e * NTOT + n0 + warp_n;
#pragma unroll
    for (int mt = 0; mt < 4; mt++) {
#pragma unroll
        for (int half = 0; half < 2; half++) {
            int m = m0 + warp_m + mt * 16 + g + half * 8;
            if (m >= cnt) continue;
            float* orow;
            if (IS_G1) {
                orow = g_H + ((size_t)e * CAP + m) * NTOT + n0 + warp_n;
            } else {
                int tok = s_tok[m - m0];
                if (g_win[tok] != e) continue;   // single winner writes
                orow = Oout + (size_t)tok * NTOT + n0 + warp_n;
            }
#pragma unroll
            for (int nt = 0; nt < 8; nt++) {
                int col = nt * 8 + 2 * tg;
                float v0 = d[mt][nt][half * 2 + 0] + bv[col];
                float v1 = d[mt][nt][half * 2 + 1] + bv[col + 1];
                if (IS_G1) {
                    v0 = 0.5f * v0 * (1.0f + erff(v0 * 0.70710678118654752f));
                    v1 = 0.5f * v1 * (1.0f + erff(v1 * 0.70710678118654752f));
                    v0 = __uint_as_float(f2tf(v0));   // round for GEMM2 input
                    v1 = __uint_as_float(f2tf(v1));
                }
                *(float2*)(orow + col) = make_float2(v0, v1);
            }
        }
    }
}

// =====================================================================
// Launch (graph-capturable: kernels + async memset only)
// =====================================================================
extern "C" void kernel_launch(void* const* d_in, const int* in_sizes, int n_in,
                              void* d_out, int out_size)
{
    const float* x     = (const float*)d_in[0];
    const float* noise = (const float*)d_in[1];
    const float* rw    = (const float*)d_in[2];
    const float* rb    = (const float*)d_in[3];
    const float* w1    = (const float*)d_in[4];
    const float* b1    = (const float*)d_in[5];
    const float* w2    = (const float*)d_in[6];
    const float* b2    = (const float*)d_in[7];
    float* out = (float*)d_out;

    cudaFuncSetAttribute(moe_gemm<DIM, DFF, true>,
                         cudaFuncAttributeMaxDynamicSharedMemorySize, GEMM_DSM);
    cudaFuncSetAttribute(moe_gemm<DFF, DIM, false>,
                         cudaFuncAttributeMaxDynamicSharedMemorySize, GEMM_DSM);

    // dropped tokens must be zero; d_out is poisoned before timing
    cudaMemsetAsync(d_out, 0, (size_t)out_size * sizeof(float), 0);

    // tf32 pre-rounding of GEMM operands (router uses original fp32 x)
    float* gx;  cudaGetSymbolAddress((void**)&gx,  g_X);
    float* gw1; cudaGetSymbolAddress((void**)&gw1, g_W1);
    float* gw2; cudaGetSymbolAddress((void**)&gw2, g_W2);
    cvt_tf32_kernel<<<1024, 256>>>((const float4*)x,  (float4*)gx,
                                   T_TOK * DIM / 4);
    cvt_tf32_kernel<<<2048, 256>>>((const float4*)w1, (float4*)gw1,
                                   NE * DIM * DFF / 4);
    cvt_tf32_kernel<<<2048, 256>>>((const float4*)w2, (float4*)gw2,
                                   NE * DFF * DIM / 4);

    router_kernel<<<T_TOK / 8, 256>>>(x, rw, rb, noise);
    assign_kernel<<<NE, 1024>>>();

    dim3 g1(DFF / BN, (CAP + BM - 1) / BM, NE);   // 32 x 26 x 8
    moe_gemm<DIM, DFF, true><<<g1, NTHR, GEMM_DSM>>>(gw1, b1, nullptr);

    dim3 g2(DIM / BN, (CAP + BM - 1) / BM, NE);   // 8 x 26 x 8
    moe_gemm<DFF, DIM, false><<<g2, NTHR, GEMM_DSM>>>(gw2, b2, out);
}

// round 12
// speedup vs baseline: 6.8935x; 1.7379x over previous
#include <cuda_runtime.h>
#include <math.h>
#include <stdint.h>

// Problem constants
#define T_TOK 16384
#define DIM   1024
#define DFF   4096
#define NE    8
#define CAP   3277          // ceil(16384 * 1.6 / 8)
#define NOISE_STD 0.02f

// ---------------- device scratch (no allocations allowed) ----------------
__device__ int   g_top1[T_TOK];
__device__ int   g_top2[T_TOK];
__device__ int   g_win [T_TOK];          // max accepted expert per token, -1 = none
__device__ int   g_widx[NE][CAP];        // per-expert WINNER token list (compacted)
__device__ int   g_wcnt[NE];             // winner count per expert
__device__ float g_H [(size_t)NE * CAP * DFF];    // gelu(x@w1+b1), tf32-rounded
__device__ float g_X [(size_t)T_TOK * DIM];       // tf32-rounded x
__device__ float g_W1[(size_t)NE * DIM * DFF];    // tf32-rounded w1
__device__ float g_W2[(size_t)NE * DFF * DIM];    // tf32-rounded w2

// =====================================================================
// PTX helpers (sm_80-level only: works on compute_103 base target)
// =====================================================================
__device__ __forceinline__ uint32_t smem_u32(const void* p) {
    uint32_t a;
    asm("{ .reg .u64 t; cvta.to.shared.u64 t, %1; cvt.u32.u64 %0, t; }"
        : "=r"(a) : "l"(p));
    return a;
}
__device__ __forceinline__ uint32_t f2tf(float f) {   // fp32 -> tf32 (round-nearest)
    uint32_t r; asm("cvt.rna.tf32.f32 %0, %1;" : "=r"(r) : "f"(f)); return r;
}
__device__ __forceinline__ void cpa16(uint32_t sdst, const void* gsrc) {
    asm volatile("cp.async.cg.shared.global [%0], [%1], 16;"
                 :: "r"(sdst), "l"(gsrc));
}
#define CP_COMMIT() asm volatile("cp.async.commit_group;" ::: "memory")
#define CP_WAIT1()  asm volatile("cp.async.wait_group 1;" ::: "memory")

// D[16x8] += A[16x8] * B[8x8], tf32 inputs (b32 regs), fp32 accum
__device__ __forceinline__ void mma8(float* d, const uint32_t* a, const uint32_t* b) {
    asm volatile(
        "mma.sync.aligned.m16n8k8.row.col.f32.tf32.tf32.f32 "
        "{%0,%1,%2,%3},{%4,%5,%6,%7},{%8,%9},{%0,%1,%2,%3};"
        : "+f"(d[0]), "+f"(d[1]), "+f"(d[2]), "+f"(d[3])
        : "r"(a[0]), "r"(a[1]), "r"(a[2]), "r"(a[3]), "r"(b[0]), "r"(b[1]));
}

// =====================================================================
// Elementwise fp32 -> tf32 rounding (pre-pass for x, w1, w2)
// =====================================================================
__global__ void cvt_tf32_kernel(const float4* __restrict__ src,
                                float4* __restrict__ dst, int n4)
{
    int i = blockIdx.x * blockDim.x + threadIdx.x;
    int stride = gridDim.x * blockDim.x;
    for (; i < n4; i += stride) {
        float4 v = src[i];
        dst[i] = make_float4(__uint_as_float(f2tf(v.x)),
                             __uint_as_float(f2tf(v.y)),
                             __uint_as_float(f2tf(v.z)),
                             __uint_as_float(f2tf(v.w)));
    }
}

// =====================================================================
// Router: logits = x @ rw^T + rb + noise*0.02 ; top-2 (ties -> lower idx)
// =====================================================================
__global__ void router_kernel(const float* __restrict__ x,
                              const float* __restrict__ rw,
                              const float* __restrict__ rb,
                              const float* __restrict__ noise)
{
    __shared__ float s_rw[NE * DIM];
    for (int i = threadIdx.x; i < NE * DIM; i += blockDim.x) s_rw[i] = rw[i];
    __syncthreads();

    int warp = threadIdx.x >> 5;
    int lane = threadIdx.x & 31;
    int t = blockIdx.x * 8 + warp;
    if (t >= T_TOK) return;

    float acc[NE];
#pragma unroll
    for (int e = 0; e < NE; e++) acc[e] = 0.f;

    const float* xr = x + (size_t)t * DIM;
#pragma unroll 4
    for (int i = lane; i < DIM; i += 32) {
        float xv = xr[i];
#pragma unroll
        for (int e = 0; e < NE; e++) acc[e] += xv * s_rw[e * DIM + i];
    }
#pragma unroll
    for (int e = 0; e < NE; e++) {
#pragma unroll
        for (int off = 16; off > 0; off >>= 1)
            acc[e] += __shfl_xor_sync(0xFFFFFFFFu, acc[e], off);
    }

    if (lane == 0) {
        float lg[NE];
#pragma unroll
        for (int e = 0; e < NE; e++)
            lg[e] = acc[e] + rb[e] + noise[t * NE + e] * NOISE_STD;

        int b1i = 0; float b1v = lg[0];
#pragma unroll
        for (int e = 1; e < NE; e++) if (lg[e] > b1v) { b1v = lg[e]; b1i = e; }
        int b2i = -1; float b2v = -3.4e38f;
#pragma unroll
        for (int e = 0; e < NE; e++)
            if (e != b1i && lg[e] > b2v) { b2v = lg[e]; b2i = e; }

        g_top1[t] = b1i;
        g_top2[t] = b2i;
        g_win[t]  = -1;
    }
}

// =====================================================================
// Assignment: per-expert ordered compaction over candidates, first CAP
// accepted (token order); winner = max accepted expert (atomicMax).
// =====================================================================
__global__ void assign_kernel()
{
    int e    = blockIdx.x;
    int tid  = threadIdx.x;
    int lane = tid & 31;
    int w    = tid >> 5;

    __shared__ int s_wsum[32];
    __shared__ int s_total;

    int base = 0;
    for (int chunk = 0; chunk < T_TOK / 1024; chunk++) {
        int t = chunk * 1024 + tid;
        int flag = (g_top1[t] == e) || (g_top2[t] == e);

        unsigned bal = __ballot_sync(0xFFFFFFFFu, flag);
        int wpre = __popc(bal & ((1u << lane) - 1u));
        if (lane == 0) s_wsum[w] = __popc(bal);
        __syncthreads();

        if (w == 0) {
            int v = s_wsum[lane];
            int inc = v;
#pragma unroll
            for (int off = 1; off < 32; off <<= 1) {
                int o = __shfl_up_sync(0xFFFFFFFFu, inc, off);
                if (lane >= off) inc += o;
            }
            s_wsum[lane] = inc - v;
            if (lane == 31) s_total = inc;
        }
        __syncthreads();

        if (flag) {
            int pos = base + s_wsum[w] + wpre;
            if (pos < CAP) atomicMax(&g_win[t], e);   // accepted -> winner cand.
        }
        base += s_total;
        __syncthreads();
    }
}

// =====================================================================
// Winner compaction: tokens with g_win[t]==e -> g_widx[e][*] (token order).
// Only winner rows feed the FFN (overwrite semantics make others dead work).
// =====================================================================
__global__ void winner_kernel()
{
    int e    = blockIdx.x;
    int tid  = threadIdx.x;
    int lane = tid & 31;
    int w    = tid >> 5;

    __shared__ int s_wsum[32];
    __shared__ int s_total;

    int base = 0;
    for (int chunk = 0; chunk < T_TOK / 1024; chunk++) {
        int t = chunk * 1024 + tid;
        int flag = (g_win[t] == e);

        unsigned bal = __ballot_sync(0xFFFFFFFFu, flag);
        int wpre = __popc(bal & ((1u << lane) - 1u));
        if (lane == 0) s_wsum[w] = __popc(bal);
        __syncthreads();

        if (w == 0) {
            int v = s_wsum[lane];
            int inc = v;
#pragma unroll
            for (int off = 1; off < 32; off <<= 1) {
                int o = __shfl_up_sync(0xFFFFFFFFu, inc, off);
                if (lane >= off) inc += o;
            }
            s_wsum[lane] = inc - v;
            if (lane == 31) s_total = inc;
        }
        __syncthreads();

        if (flag) g_widx[e][base + s_wsum[w] + wpre] = t;
        base += s_total;
        __syncthreads();
    }
    if (tid == 0) g_wcnt[e] = base;      // always <= CAP (winners are accepted)
}

// =====================================================================
// tf32 mma.sync GEMM: CTA tile 128x128x32, 4 warps (2x2), warp tile 64x64.
// cp.async double-buffered. A rows = winner tokens only.
//   G1: H = tf32round( gelu( gather(gX) @ gW1 + b1 ) )   K=1024, N=4096
//   G2: out[token] = H @ gW2 + b2 (unconditional)        K=4096, N=1024
// =====================================================================
#define BM 128
#define BN 128
#define BK 32
#define NTHR 128
#define A_STAGE 16384                 // BM rows x 128B (XOR-swizzled 16B chunks)
#define B_ROWB  528                   // (BN + 4 pad) * 4B
#define B_STAGE (BK * B_ROWB)         // 16896
#define STAGE_B (A_STAGE + B_STAGE)   // 33280
#define GEMM_DSM (2 * STAGE_B)        // 66560

template<int KTOT, int NTOT, bool IS_G1>
__global__ __launch_bounds__(NTHR, 2) void moe_gemm(
    const float* __restrict__ W,       // tf32-rounded weights [E][KTOT][NTOT]
    const float* __restrict__ bias,    // [E][NTOT] (fp32)
    float* __restrict__ Oout)          // out (G2) / unused (G1)
{
    const int e   = blockIdx.z;
    const int cnt = g_wcnt[e];
    const int m0  = blockIdx.y * BM;
    if (m0 >= cnt) return;
    const int n0  = blockIdx.x * BN;

    extern __shared__ char dsm[];
    const uint32_t sbase = smem_u32(dsm);

    __shared__ int s_tok[BM];

    const int tid = threadIdx.x;
    {
        int m = m0 + tid; if (m >= cnt) m = cnt - 1;
        s_tok[tid] = g_widx[e][m];
    }
    __syncthreads();

    // ---- cp.async A: chunk col = tid&7 (16B), rows (tid>>3) + 16*i ----
    const int a_c  = tid & 7;
    const int a_r0 = tid >> 3;
    const uint32_t a_swz = ((uint32_t)(a_c ^ (a_r0 & 7)) << 4);
    const char* a_src[8];
    const uint32_t a_dst0 = sbase + a_r0 * 128 + a_swz;
#pragma unroll
    for (int i = 0; i < 8; i++) {
        int r = a_r0 + 16 * i;
        const float* rowp;
        if (IS_G1) {
            rowp = g_X + (size_t)s_tok[r] * KTOT;
        } else {
            int m = m0 + r; if (m >= cnt) m = cnt - 1;
            rowp = g_H + ((size_t)e * CAP + m) * KTOT;
        }
        a_src[i] = (const char*)rowp + a_c * 16;
    }
    // ---- cp.async B: col chunk tid&31 (16B), k rows (tid>>5) + 4*i ----
    const int b_j  = tid & 31;
    const int b_k0 = tid >> 5;
    const char* b_src0 = (const char*)(W + ((size_t)e * KTOT + b_k0) * NTOT
                                       + n0 + b_j * 4);
    const uint32_t b_dst0 = sbase + A_STAGE + b_k0 * B_ROWB + b_j * 16;

    // ---- fragment indexing ----
    const int lane = tid & 31;
    const int wid  = tid >> 5;
    const int g    = lane >> 2;       // group 0..7
    const int tg   = lane & 3;        // thread-in-group 0..3
    const int warp_m = (wid >> 1) * 64;
    const int warp_n = (wid & 1) * 64;

    float d[4][8][4];
#pragma unroll
    for (int mt = 0; mt < 4; mt++)
#pragma unroll
        for (int nt = 0; nt < 8; nt++)
#pragma unroll
            for (int q = 0; q < 4; q++) d[mt][nt][q] = 0.f;

    const int S = KTOT / BK;

    // prologue: stage 0
    {
        const size_t bks = (size_t)4 * NTOT * 4;
#pragma unroll
        for (int i = 0; i < 8; i++) cpa16(a_dst0 + i * 2048u, a_src[i]);
#pragma unroll
        for (int i = 0; i < 8; i++) cpa16(b_dst0 + i * 4u * B_ROWB, b_src0 + i * bks);
    }
    CP_COMMIT();

    for (int s = 0; s < S; s++) {
        if (s + 1 < S) {
            const uint32_t soff = (uint32_t)((s + 1) & 1) * STAGE_B;
            const size_t akoff = (size_t)(s + 1) * (BK * 4);
            const size_t bkoff = (size_t)(s + 1) * ((size_t)BK * NTOT * 4);
            const size_t bks   = (size_t)4 * NTOT * 4;
#pragma unroll
            for (int i = 0; i < 8; i++)
                cpa16(a_dst0 + soff + i * 2048u, a_src[i] + akoff);
#pragma unroll
            for (int i = 0; i < 8; i++)
                cpa16(b_dst0 + soff + i * 4u * B_ROWB, b_src0 + bkoff + i * bks);
        }
        CP_COMMIT();
        CP_WAIT1();
        __syncthreads();

        const uint32_t sA = sbase + (uint32_t)(s & 1) * STAGE_B;
        const uint32_t sB = sA + A_STAGE;

#pragma unroll
        for (int ks = 0; ks < 4; ks++) {
            uint32_t a[4][4];
#pragma unroll
            for (int mt = 0; mt < 4; mt++) {
                uint32_t rb_ = sA + (uint32_t)(warp_m + mt * 16 + g) * 128u
                             + ((uint32_t)((2 * ks + (tg >> 1)) ^ g) << 4)
                             + (uint32_t)(tg & 1) * 8u;
                asm("ld.shared.v2.b32 {%0,%1},[%2];"
                    : "=r"(a[mt][0]), "=r"(a[mt][2]) : "r"(rb_));
                asm("ld.shared.v2.b32 {%0,%1},[%2];"
                    : "=r"(a[mt][1]), "=r"(a[mt][3]) : "r"(rb_ + 8u * 128u));
            }
            uint32_t b[8][2];
#pragma unroll
            for (int nt = 0; nt < 8; nt++) {
                uint32_t cb = sB + (uint32_t)(8 * ks + 2 * tg) * B_ROWB
                            + (uint32_t)(warp_n + nt * 8 + g) * 4u;
                asm("ld.shared.b32 %0,[%1];" : "=r"(b[nt][0]) : "r"(cb));
                asm("ld.shared.b32 %0,[%1];" : "=r"(b[nt][1]) : "r"(cb + B_ROWB));
            }
#pragma unroll
            for (int mt = 0; mt < 4; mt++)
#pragma unroll
                for (int nt = 0; nt < 8; nt++)
                    mma8(d[mt][nt], a[mt], b[nt]);
        }
        __syncthreads();
    }

    // ---- epilogue (every surviving row is a winner row) ----
    const float* bv = bias + (size_t)e * NTOT + n0 + warp_n;
#pragma unroll
    for (int mt = 0; mt < 4; mt++) {
#pragma unroll
        for (int half = 0; half < 2; half++) {
            int m = m0 + warp_m + mt * 16 + g + half * 8;
            if (m >= cnt) continue;
            float* orow;
            if (IS_G1) {
                orow = g_H + ((size_t)e * CAP + m) * NTOT + n0 + warp_n;
            } else {
                int tok = s_tok[m - m0];
                orow = Oout + (size_t)tok * NTOT + n0 + warp_n;
            }
#pragma unroll
            for (int nt = 0; nt < 8; nt++) {
                int col = nt * 8 + 2 * tg;
                float v0 = d[mt][nt][half * 2 + 0] + bv[col];
                float v1 = d[mt][nt][half * 2 + 1] + bv[col + 1];
                if (IS_G1) {
                    v0 = 0.5f * v0 * (1.0f + erff(v0 * 0.70710678118654752f));
                    v1 = 0.5f * v1 * (1.0f + erff(v1 * 0.70710678118654752f));
                    v0 = __uint_as_float(f2tf(v0));   // round for GEMM2 input
                    v1 = __uint_as_float(f2tf(v1));
                }
                *(float2*)(orow + col) = make_float2(v0, v1);
            }
        }
    }
}

// =====================================================================
// Launch (graph-capturable: kernels + async memset only)
// =====================================================================
extern "C" void kernel_launch(void* const* d_in, const int* in_sizes, int n_in,
                              void* d_out, int out_size)
{
    const float* x     = (const float*)d_in[0];
    const float* noise = (const float*)d_in[1];
    const float* rw    = (const float*)d_in[2];
    const float* rb    = (const float*)d_in[3];
    const float* w1    = (const float*)d_in[4];
    const float* b1    = (const float*)d_in[5];
    const float* w2    = (const float*)d_in[6];
    const float* b2    = (const float*)d_in[7];
    float* out = (float*)d_out;

    cudaFuncSetAttribute(moe_gemm<DIM, DFF, true>,
                         cudaFuncAttributeMaxDynamicSharedMemorySize, GEMM_DSM);
    cudaFuncSetAttribute(moe_gemm<DFF, DIM, false>,
                         cudaFuncAttributeMaxDynamicSharedMemorySize, GEMM_DSM);

    // dropped tokens must be zero; d_out is poisoned before timing
    cudaMemsetAsync(d_out, 0, (size_t)out_size * sizeof(float), 0);

    // tf32 pre-rounding of GEMM operands (router uses original fp32 x)
    float* gx;  cudaGetSymbolAddress((void**)&gx,  g_X);
    float* gw1; cudaGetSymbolAddress((void**)&gw1, g_W1);
    float* gw2; cudaGetSymbolAddress((void**)&gw2, g_W2);
    cvt_tf32_kernel<<<1024, 256>>>((const float4*)x,  (float4*)gx,
                                   T_TOK * DIM / 4);
    cvt_tf32_kernel<<<2048, 256>>>((const float4*)w1, (float4*)gw1,
                                   NE * DIM * DFF / 4);
    cvt_tf32_kernel<<<2048, 256>>>((const float4*)w2, (float4*)gw2,
                                   NE * DFF * DIM / 4);

    router_kernel<<<T_TOK / 8, 256>>>(x, rw, rb, noise);
    assign_kernel<<<NE, 1024>>>();
    winner_kernel<<<NE, 1024>>>();

    dim3 g1(DFF / BN, (CAP + BM - 1) / BM, NE);   // 32 x 26 x 8
    moe_gemm<DIM, DFF, true><<<g1, NTHR, GEMM_DSM>>>(gw1, b1, nullptr);

    dim3 g2(DIM / BN, (CAP + BM - 1) / BM, NE);   // 8 x 26 x 8
    moe_gemm<DFF, DIM, false><<<g2, NTHR, GEMM_DSM>>>(gw2, b2, out);
}